// round 5
// baseline (speedup 1.0000x reference)
#include <cuda_runtime.h>
#include <cstdint>
#include <math_constants.h>

#define IN_DIM   128
#define HID      64
#define G_MAX    8192
#define CHUNK    128
#define THREADS  128
#define XS_STRIDE 129   // 128 + 1 pad -> conflict-free LDS in MLP and pool phases

// Shared memory layout (bytes)
#define XS_FLOATS   (CHUNK * XS_STRIDE)             // 16512 floats = 66048 B
#define WS_OFF      (XS_FLOATS * 4)                 // 66048 (16B aligned)
#define WS_U64      (IN_DIM * (HID / 2))            // 4096 u64 = 32768 B
#define B1_OFF      (WS_OFF + WS_U64 * 8)           // 98816
#define W2_OFF      (B1_OFF + HID * 4)              // 99072
#define ES_OFF      (W2_OFF + HID * 4)              // 99328
#define RED_OFF     (ES_OFF + CHUNK * 4)            // 99840
#define SMEM_TOTAL  (RED_OFF + 32 * 4)              // 99968 B  (2 CTAs/SM)

__device__ int g_seg_start[G_MAX + 1];

// ---------------------------------------------------------------------------
// Kernel 1: segment offsets from sorted batch (int32 view, stride 1 or 2).
// Inline dtype detect: view buffer as int32 (safe for both dtypes). Little-
// endian int64 -> odd int32 indices are high words (values < 8192 -> 0).
// int32 -> the sorted value at the middle is ~G/2 != 0. Broadcast load.
// seg_start[g] = first index i with batch[i] >= g;  seg_start[G] = N.
// ---------------------------------------------------------------------------
__global__ void seg_offsets_kernel(const int* __restrict__ b32, int n, int G)
{
    int i = blockIdx.x * blockDim.x + threadIdx.x;
    if (i > n) return;
    const int s = (b32[(n / 2) | 1] == 0) ? 2 : 1;   // int64 -> stride 2 (low word)
    int cur  = (i < n) ? b32[(size_t)i * s]       : G;
    int prev = (i > 0) ? b32[(size_t)(i - 1) * s] : -1;
    cur  = min(max(cur,  -1), G);        // clamp: garbage can never index OOB
    prev = min(max(prev, -1), G);
    for (int g = prev + 1; g <= cur; ++g)
        g_seg_start[g] = i;              // g in [0, G] subset of [0, G_MAX]
}

// packed f32x2 FMA (FFMA2) — only reachable via PTX, 2x tput vs scalar FFMA
__device__ __forceinline__ unsigned long long ffma2(unsigned long long a,
                                                    unsigned long long b,
                                                    unsigned long long c)
{
    unsigned long long d;
    asm("fma.rn.f32x2 %0, %1, %2, %3;" : "=l"(d) : "l"(a), "l"(b), "l"(c));
    return d;
}

__device__ __forceinline__ unsigned long long pack_dup(float x)
{
    unsigned long long r;
    uint32_t xu = __float_as_uint(x);
    asm("mov.b64 %0, {%1, %1};" : "=l"(r) : "r"(xu));
    return r;
}

__device__ __forceinline__ void unpack2(unsigned long long v, float& lo, float& hi)
{
    uint32_t l, h;
    asm("mov.b64 {%0, %1}, %2;" : "=r"(l), "=r"(h) : "l"(v));
    lo = __uint_as_float(l);
    hi = __uint_as_float(h);
}

// ---------------------------------------------------------------------------
// Kernel 2: fused gate-MLP + online segment softmax + weighted pooling.
// One CTA per graph; nodes processed in 128-node chunks staged in SMEM.
// x is read from DRAM exactly once. MLP computed in two HID-halves to keep
// live accumulators at 16 u64 (32 regs) and avoid spills.
// ---------------------------------------------------------------------------
__global__ __launch_bounds__(THREADS)
void attn_pool_kernel(const float* __restrict__ x,
                      const float* __restrict__ W1,
                      const float* __restrict__ b1,
                      const float* __restrict__ W2,
                      const float* __restrict__ b2,
                      float* __restrict__ out)
{
    extern __shared__ char smem[];
    float*              xs  = (float*)smem;                         // [CHUNK][129]
    unsigned long long* ws  = (unsigned long long*)(smem + WS_OFF); // W1 as f32 pairs
    float*              b1s = (float*)(smem + B1_OFF);
    float*              w2s = (float*)(smem + W2_OFF);
    float*              es  = (float*)(smem + ES_OFF);              // exp weights
    float*              red = (float*)(smem + RED_OFF);             // reduce scratch

    const int tid  = threadIdx.x;
    const int lane = tid & 31;
    const int wid  = tid >> 5;
    const int g    = blockIdx.x;

    const int start = g_seg_start[g];
    const int end   = g_seg_start[g + 1];

    // Stage weights: W1 row-major [128][64] -> float2 pairs, identical layout.
    {
        const unsigned long long* w1u = (const unsigned long long*)W1;
        for (int i = tid; i < WS_U64; i += THREADS) ws[i] = w1u[i];
        if (tid < HID) { b1s[tid] = b1[tid]; w2s[tid] = W2[tid]; }
    }
    const float b2v = b2[0];

    float m_run = -CUDART_INF_F;
    float s_run = 0.f;
    float acc   = 0.f;   // thread tid owns output dim tid

    for (int cs = start; cs < end; cs += CHUNK) {
        const int c = min(CHUNK, end - cs);
        __syncthreads();   // xs/es from previous chunk fully consumed

        // ---- load x chunk (coalesced float4 LDG, scalar STS into padded rows)
        {
            const float4* x4 = (const float4*)x;
            const int total = c * (IN_DIM / 4);
            for (int i = tid; i < total; i += THREADS) {
                const int row = i >> 5;      // node within chunk
                const int c4  = i & 31;      // float4 column
                float4 v = x4[(size_t)(cs + row) * (IN_DIM / 4) + c4];
                float* dst = xs + row * XS_STRIDE + c4 * 4;
                dst[0] = v.x; dst[1] = v.y; dst[2] = v.z; dst[3] = v.w;
            }
        }
        __syncthreads();

        // ---- gate MLP: one node per thread, FFMA2 packed accumulators.
        // Two passes over HID halves: only 16 u64 accumulators live at a time.
        float gate = -CUDART_INF_F;
        if (tid < c) {
            const float* xr = xs + tid * XS_STRIDE;   // conflict-free by pad
            float gacc = b2v;
            #pragma unroll 1
            for (int half = 0; half < 2; ++half) {
                unsigned long long h[HID / 4];        // 16 u64 = 32 regs
                const unsigned long long zero2 = pack_dup(0.f);
                #pragma unroll
                for (int p = 0; p < HID / 4; ++p) h[p] = zero2;

                const int hoff = half * (HID / 4);    // offset in f32-pair units
                #pragma unroll 1
                for (int k = 0; k < IN_DIM; ++k) {
                    const unsigned long long x2 = pack_dup(xr[k]);
                    const ulonglong2* wr =
                        (const ulonglong2*)(ws + k * (HID / 2) + hoff);
                    #pragma unroll
                    for (int p = 0; p < HID / 8; ++p) {   // 8 x LDS.128
                        ulonglong2 wv = wr[p];
                        h[2 * p]     = ffma2(x2, wv.x, h[2 * p]);
                        h[2 * p + 1] = ffma2(x2, wv.y, h[2 * p + 1]);
                    }
                }
                const int jbase = half * (HID / 2);
                #pragma unroll
                for (int p = 0; p < HID / 4; ++p) {
                    float lo, hi;
                    unpack2(h[p], lo, hi);
                    lo = fmaxf(lo + b1s[jbase + 2 * p], 0.f);
                    hi = fmaxf(hi + b1s[jbase + 2 * p + 1], 0.f);
                    gacc = fmaf(lo, w2s[jbase + 2 * p], gacc);
                    gacc = fmaf(hi, w2s[jbase + 2 * p + 1], gacc);
                }
            }
            gate = gacc;
        }

        // ---- chunk max (warp shuffle + smem)
        float v = gate;
        #pragma unroll
        for (int o = 16; o; o >>= 1) v = fmaxf(v, __shfl_xor_sync(0xffffffffu, v, o));
        if (lane == 0) red[wid] = v;
        __syncthreads();
        const float cmax  = fmaxf(fmaxf(red[0], red[1]), fmaxf(red[2], red[3]));
        const float m_new = fmaxf(m_run, cmax);
        const float resc  = expf(m_run - m_new);   // first chunk: exp(-inf) = 0

        const float e = (tid < c) ? expf(gate - m_new) : 0.f;
        __syncthreads();   // everyone done reading red (max) before reuse
        es[tid] = e;
        float sv = e;
        #pragma unroll
        for (int o = 16; o; o >>= 1) sv += __shfl_xor_sync(0xffffffffu, sv, o);
        if (lane == 0) red[wid] = sv;
        __syncthreads();
        const float csum = red[0] + red[1] + red[2] + red[3];

        s_run = s_run * resc + csum;
        m_run = m_new;

        // ---- weighted accumulate: thread d sums e[n]*xs[n][d] (conflict-free)
        acc *= resc;
        {
            const float4* e4 = (const float4*)es;
            const int n4max = c >> 2;
            #pragma unroll 2
            for (int n4 = 0; n4 < n4max; ++n4) {
                float4 ev = e4[n4];
                const float* xcol = xs + (n4 * 4) * XS_STRIDE + tid;
                acc = fmaf(ev.x, xcol[0 * XS_STRIDE], acc);
                acc = fmaf(ev.y, xcol[1 * XS_STRIDE], acc);
                acc = fmaf(ev.z, xcol[2 * XS_STRIDE], acc);
                acc = fmaf(ev.w, xcol[3 * XS_STRIDE], acc);
            }
            for (int n = n4max * 4; n < c; ++n)
                acc = fmaf(es[n], xs[n * XS_STRIDE + tid], acc);
        }
    }

    out[(size_t)g * IN_DIM + tid] = (end > start) ? (acc / s_run) : 0.f;
}

// ---------------------------------------------------------------------------
extern "C" void kernel_launch(void* const* d_in, const int* in_sizes, int n_in,
                              void* d_out, int out_size)
{
    const float* x   = (const float*)d_in[0];
    const int*   b32 = (const int*)d_in[1];   // int32 view: safe for i32/i64
    const float* W1  = (const float*)d_in[2];
    const float* b1  = (const float*)d_in[3];
    const float* W2  = (const float*)d_in[4];
    const float* b2  = (const float*)d_in[5];
    float*       out = (float*)d_out;

    const int N = in_sizes[0] / IN_DIM;
    int G = out_size / IN_DIM;
    if (G > G_MAX) G = G_MAX;

    seg_offsets_kernel<<<(N + 1 + 255) / 256, 256>>>(b32, N, G);

    cudaFuncSetAttribute(attn_pool_kernel,
                         cudaFuncAttributeMaxDynamicSharedMemorySize, SMEM_TOTAL);
    attn_pool_kernel<<<G, THREADS, SMEM_TOTAL>>>(x, W1, b1, W2, b2, out);
}

// round 6
// speedup vs baseline: 1.4658x; 1.4658x over previous
#include <cuda_runtime.h>
#include <cstdint>
#include <math_constants.h>

#define IN_DIM   128
#define HID      64
#define G_MAX    8192
#define CHUNK    128
#define THREADS  128
#define XT       132   // xs_t row stride (floats): 4*XT % 128B -> conflict-free ld/st

// Shared memory layout (bytes)
#define XS_BYTES    (IN_DIM * XT * 4)               // 67584: xs_t[dim][node]
#define WS_OFF      XS_BYTES                         // W1 as f32 pairs [k][HID/2]
#define WS_U64      (IN_DIM * (HID / 2))             // 4096 u64 = 32768 B
#define B1_OFF      (WS_OFF + WS_U64 * 8)
#define W2_OFF      (B1_OFF + HID * 4)
#define ES_OFF      (W2_OFF + HID * 4)               // gates, then exp weights
#define RED_OFF     (ES_OFF + CHUNK * 4)
#define SMEM_TOTAL  (RED_OFF + 32 * 4)               // ~101.5 KB -> 2 CTAs/SM

__device__ int g_seg_start[G_MAX + 1];

// ---------------------------------------------------------------------------
// Kernel 1: segment offsets from sorted batch (int32 view; inline i64 detect).
// ---------------------------------------------------------------------------
__global__ void seg_offsets_kernel(const int* __restrict__ b32, int n, int G)
{
    int i = blockIdx.x * blockDim.x + threadIdx.x;
    if (i > n) return;
    const int s = (b32[(n / 2) | 1] == 0) ? 2 : 1;   // int64 -> stride 2 (low word)
    int cur  = (i < n) ? b32[(size_t)i * s]       : G;
    int prev = (i > 0) ? b32[(size_t)(i - 1) * s] : -1;
    cur  = min(max(cur,  -1), G);
    prev = min(max(prev, -1), G);
    for (int g = prev + 1; g <= cur; ++g)
        g_seg_start[g] = i;
}

// packed f32x2 FMA — PTX-only, 2x tput vs scalar FFMA
__device__ __forceinline__ unsigned long long ffma2(unsigned long long a,
                                                    unsigned long long b,
                                                    unsigned long long c)
{
    unsigned long long d;
    asm("fma.rn.f32x2 %0, %1, %2, %3;" : "=l"(d) : "l"(a), "l"(b), "l"(c));
    return d;
}

__device__ __forceinline__ unsigned long long pack_dup(float x)
{
    unsigned long long r;
    uint32_t xu = __float_as_uint(x);
    asm("mov.b64 %0, {%1, %1};" : "=l"(r) : "r"(xu));
    return r;
}

__device__ __forceinline__ void unpack2(unsigned long long v, float& lo, float& hi)
{
    uint32_t l, h;
    asm("mov.b64 {%0, %1}, %2;" : "=r"(l), "=r"(h) : "l"(v));
    lo = __uint_as_float(l);
    hi = __uint_as_float(h);
}

// ---------------------------------------------------------------------------
// Kernel 2: fused gate-MLP (register-tiled) + online softmax + pooling.
// One CTA per graph. xs staged TRANSPOSED: xs_t[dim][node], stride XT=132.
// MLP tile: thread = (ngrp 0..15, hgrp 0..7) computes 8 nodes x 8 hid.
// ---------------------------------------------------------------------------
__global__ __launch_bounds__(THREADS)
void attn_pool_kernel(const float* __restrict__ x,
                      const float* __restrict__ W1,
                      const float* __restrict__ b1,
                      const float* __restrict__ W2,
                      const float* __restrict__ b2,
                      float* __restrict__ out)
{
    extern __shared__ char smem[];
    float*              xs  = (float*)smem;                         // [128][XT]
    unsigned long long* ws  = (unsigned long long*)(smem + WS_OFF);
    float*              b1s = (float*)(smem + B1_OFF);
    float*              w2s = (float*)(smem + W2_OFF);
    float*              es  = (float*)(smem + ES_OFF);              // gates / e
    float*              red = (float*)(smem + RED_OFF);

    const int tid  = threadIdx.x;
    const int lane = tid & 31;
    const int wid  = tid >> 5;
    const int hgrp = tid & 7;        // hid group: hid = hgrp*8 + j
    const int ngrp = tid >> 3;       // node group: node = ngrp*8 + i
    const int g    = blockIdx.x;

    const int start = g_seg_start[g];
    const int end   = g_seg_start[g + 1];

    // Stage weights (reused across chunks)
    {
        const unsigned long long* w1u = (const unsigned long long*)W1;
        for (int i = tid; i < WS_U64; i += THREADS) ws[i] = w1u[i];
        if (tid < HID) { b1s[tid] = b1[tid]; w2s[tid] = W2[tid]; }
    }
    const float b2v = b2[0];

    float m_run = -CUDART_INF_F;
    float s_run = 0.f;
    float acc   = 0.f;   // thread tid owns output dim tid

    for (int cs = start; cs < end; cs += CHUNK) {
        const int c = min(CHUNK, end - cs);
        __syncthreads();   // xs/es fully consumed

        // ---- load x chunk, transposed: thread tid = dim, iterate node quads.
        // Scalar LDGs coalesce (lanes span consecutive dims of one node);
        // STS.128 along node dim is conflict-free (4*XT % 32banks = 16 -> lanes
        // 0..7 start banks 0,4,...,28). Pad nodes >= c with zeros.
        {
            const float* xb = x + (size_t)cs * IN_DIM + tid;
            #pragma unroll 4
            for (int q = 0; q < CHUNK / 4; ++q) {
                float4 v;
                v.x = (4 * q + 0 < c) ? xb[(size_t)(4 * q + 0) * IN_DIM] : 0.f;
                v.y = (4 * q + 1 < c) ? xb[(size_t)(4 * q + 1) * IN_DIM] : 0.f;
                v.z = (4 * q + 2 < c) ? xb[(size_t)(4 * q + 2) * IN_DIM] : 0.f;
                v.w = (4 * q + 3 < c) ? xb[(size_t)(4 * q + 3) * IN_DIM] : 0.f;
                *(float4*)(xs + tid * XT + 4 * q) = v;
            }
        }
        __syncthreads();

        // ---- gate MLP: 8x8 register tile per thread, FFMA2 accumulators
        {
            unsigned long long h[32];             // [node i][pair p] = h[i*4+p]
            const unsigned long long zero2 = pack_dup(0.f);
            #pragma unroll
            for (int t = 0; t < 32; ++t) h[t] = zero2;

            const float*              xrow = xs + ngrp * 8;        // + k*XT
            const unsigned long long* wrow = ws + hgrp * 4;        // + k*(HID/2)

            #pragma unroll 1
            for (int k = 0; k < IN_DIM; ++k) {
                const float4 xa = *(const float4*)(xrow + k * XT);
                const float4 xb4 = *(const float4*)(xrow + k * XT + 4);
                const ulonglong2 w0 = *(const ulonglong2*)(wrow + k * (HID / 2));
                const ulonglong2 w1v = *(const ulonglong2*)(wrow + k * (HID / 2) + 2);
                unsigned long long xd[8];
                xd[0] = pack_dup(xa.x);  xd[1] = pack_dup(xa.y);
                xd[2] = pack_dup(xa.z);  xd[3] = pack_dup(xa.w);
                xd[4] = pack_dup(xb4.x); xd[5] = pack_dup(xb4.y);
                xd[6] = pack_dup(xb4.z); xd[7] = pack_dup(xb4.w);
                #pragma unroll
                for (int i = 0; i < 8; ++i) {
                    h[i * 4 + 0] = ffma2(xd[i], w0.x,  h[i * 4 + 0]);
                    h[i * 4 + 1] = ffma2(xd[i], w0.y,  h[i * 4 + 1]);
                    h[i * 4 + 2] = ffma2(xd[i], w1v.x, h[i * 4 + 2]);
                    h[i * 4 + 3] = ffma2(xd[i], w1v.y, h[i * 4 + 3]);
                }
            }

            // epilogue: relu + W2 partial per node, reduce across 8 hgrp lanes
            float partial[8];
            #pragma unroll
            for (int i = 0; i < 8; ++i) {
                float p = 0.f;
                #pragma unroll
                for (int pp = 0; pp < 4; ++pp) {
                    float lo, hi;
                    unpack2(h[i * 4 + pp], lo, hi);
                    const int j = hgrp * 8 + 2 * pp;
                    lo = fmaxf(lo + b1s[j], 0.f);
                    hi = fmaxf(hi + b1s[j + 1], 0.f);
                    p = fmaf(lo, w2s[j], p);
                    p = fmaf(hi, w2s[j + 1], p);
                }
                partial[i] = p;
            }
            #pragma unroll
            for (int off = 1; off < 8; off <<= 1)
                #pragma unroll
                for (int i = 0; i < 8; ++i)
                    partial[i] += __shfl_xor_sync(0xffffffffu, partial[i], off, 8);

            float gsel = partial[0];
            #pragma unroll
            for (int i = 1; i < 8; ++i) if (hgrp == i) gsel = partial[i];
            const int node = ngrp * 8 + hgrp;
            es[node] = (node < c) ? (gsel + b2v) : -CUDART_INF_F;
        }
        __syncthreads();

        // ---- softmax: thread tid owns node tid's gate
        const float gate = es[tid];
        float v = gate;
        #pragma unroll
        for (int o = 16; o; o >>= 1) v = fmaxf(v, __shfl_xor_sync(0xffffffffu, v, o));
        if (lane == 0) red[wid] = v;
        __syncthreads();
        const float cmax  = fmaxf(fmaxf(red[0], red[1]), fmaxf(red[2], red[3]));
        const float m_new = fmaxf(m_run, cmax);
        const float resc  = expf(m_run - m_new);   // first chunk: exp(-inf) = 0

        const float e = expf(gate - m_new);        // pad gates -inf -> e = 0
        __syncthreads();   // gates fully read before overwrite
        es[tid] = e;
        float sv = e;
        #pragma unroll
        for (int o = 16; o; o >>= 1) sv += __shfl_xor_sync(0xffffffffu, sv, o);
        if (lane == 0) red[wid] = sv;
        __syncthreads();
        const float csum = red[0] + red[1] + red[2] + red[3];

        s_run = s_run * resc + csum;
        m_run = m_new;

        // ---- weighted accumulate: thread d reads xs_t[d][n..n+3] (LDS.128,
        // conflict-free) and es quad (broadcast). Padded nodes: e=0, x=0.
        acc *= resc;
        {
            const float4* e4   = (const float4*)es;
            const float*  xrow = xs + tid * XT;
            #pragma unroll 4
            for (int n4 = 0; n4 < CHUNK / 4; ++n4) {
                const float4 ev = e4[n4];
                const float4 xv = *(const float4*)(xrow + 4 * n4);
                acc = fmaf(ev.x, xv.x, acc);
                acc = fmaf(ev.y, xv.y, acc);
                acc = fmaf(ev.z, xv.z, acc);
                acc = fmaf(ev.w, xv.w, acc);
            }
        }
    }

    out[(size_t)g * IN_DIM + tid] = (end > start) ? (acc / s_run) : 0.f;
}

// ---------------------------------------------------------------------------
extern "C" void kernel_launch(void* const* d_in, const int* in_sizes, int n_in,
                              void* d_out, int out_size)
{
    const float* x   = (const float*)d_in[0];
    const int*   b32 = (const int*)d_in[1];   // int32 view: safe for i32/i64
    const float* W1  = (const float*)d_in[2];
    const float* b1  = (const float*)d_in[3];
    const float* W2  = (const float*)d_in[4];
    const float* b2  = (const float*)d_in[5];
    float*       out = (float*)d_out;

    const int N = in_sizes[0] / IN_DIM;
    int G = out_size / IN_DIM;
    if (G > G_MAX) G = G_MAX;

    seg_offsets_kernel<<<(N + 1 + 255) / 256, 256>>>(b32, N, G);

    cudaFuncSetAttribute(attn_pool_kernel,
                         cudaFuncAttributeMaxDynamicSharedMemorySize, SMEM_TOTAL);
    attn_pool_kernel<<<G, THREADS, SMEM_TOTAL>>>(x, W1, b1, W2, b2, out);
}